// round 1
// baseline (speedup 1.0000x reference)
#include <cuda_runtime.h>

// LinearSpline: y = lerp over slope-clipped B-spline coefficients, per-channel.
// x: [32, 64, 128, 128] f32, coefficients_vect: [64*51] f32, scaling: [64] f32.

#define NCH   64
#define SZ    51
#define HALF  25                      // SIZE // 2
// Constants computed in double (matching Python) then narrowed to f32,
// exactly as JAX does when mixing python floats with f32 arrays.
#define GRID_D   (2.0 * 1.0 / (SZ - 1))          // 0.04
#define GRID_F   ((float)GRID_D)
#define CLAMP_LO ((float)(-(GRID_D * HALF)))     // -1.0
#define CLAMP_HI ((float)(GRID_D * (HALF - 1)))  // 0.96

__device__ float g_cv[NCH * SZ];

// --- prologue: slope clipping -> cumsum -> recenter at middle knot ---------
__global__ void lipschitz_kernel(const float* __restrict__ coeff) {
    int c = threadIdx.x;
    if (c >= NCH) return;
    const float* cs = coeff + c * SZ;
    float vals[SZ];
    vals[0] = 0.0f;
    float acc = 0.0f;
    float prev = cs[0];
#pragma unroll
    for (int i = 1; i < SZ; ++i) {
        float cur = cs[i];
        float slope = fminf(fmaxf(cur - prev, 0.0f), GRID_F);
        acc += slope;
        vals[i] = acc;
        prev = cur;
    }
    float mid = vals[HALF];
    float* dst = g_cv + c * SZ;
#pragma unroll
    for (int i = 0; i < SZ; ++i) dst[i] = vals[i] - mid;
}

// --- main elementwise spline eval ------------------------------------------
__global__ void __launch_bounds__(256)
spline_kernel(const float4* __restrict__ x,
              const float* __restrict__ scale,
              float4* __restrict__ out,
              int n4) {
    int i = blockIdx.x * blockDim.x + threadIdx.x;
    if (i >= n4) return;

    // element index = 4*i ; channel = (4*i / 16384) % 64 = (i >> 12) & 63
    int c = (i >> 12) & (NCH - 1);
    float s = __ldg(scale + c);
    const float* __restrict__ cv = g_cv + c * SZ;

    float4 v = x[i];
    float xin[4] = {v.x, v.y, v.z, v.w};
    float r[4];

#pragma unroll
    for (int k = 0; k < 4; ++k) {
        float xs = xin[k] * s;
        float xc = fminf(fmaxf(xs, CLAMP_LO), CLAMP_HI);
        float fl = floorf(xc / GRID_F);
        float fr = xs / GRID_F - fl;          // frac uses UNCLAMPED xs (ref semantics)
        int idx  = HALF + (int)fl;            // in [0, 49]
        float c0 = __ldg(cv + idx);
        float c1 = __ldg(cv + idx + 1);
        r[k] = (c1 * fr + c0 * (1.0f - fr)) / s;
    }

    out[i] = make_float4(r[0], r[1], r[2], r[3]);
}

extern "C" void kernel_launch(void* const* d_in, const int* in_sizes, int n_in,
                              void* d_out, int out_size) {
    const float* x     = (const float*)d_in[0];
    const float* coeff = (const float*)d_in[1];
    const float* scl   = (const float*)d_in[2];
    float* out = (float*)d_out;

    lipschitz_kernel<<<1, NCH>>>(coeff);

    int n  = out_size;        // 33554432
    int n4 = n / 4;           // 8388608
    int threads = 256;
    int blocks = (n4 + threads - 1) / threads;
    spline_kernel<<<blocks, threads>>>((const float4*)x, scl, (float4*)out, n4);
}

// round 2
// speedup vs baseline: 1.4316x; 1.4316x over previous
#include <cuda_runtime.h>

// LinearSpline: per-channel slope-clipped linear spline activation.
// x: [32, 64, 128, 128] f32, coefficients_vect: [64*51] f32, scaling: [64] f32.

#define NCH   64
#define SZ    51
#define HALF  25                               // SIZE // 2
#define GRID_D   (2.0 * 1.0 / (SZ - 1))        // 0.04 (double, matches python)
#define GRID_F   ((float)GRID_D)
#define CLAMP_LO ((float)(-(GRID_D * HALF)))   // -1.0f
#define CLAMP_HI ((float)(GRID_D * (HALF - 1)))// 0.96f
#define INV_GRID (1.0f / GRID_F)               // folds to exactly 25.0f
#define FLOOR_EPS 1e-6f                        // fixes top-clamp floor (23.99999946 -> 24)

// Pair table: g_tab[c*50 + j] = { cv[j], cv[j+1]-cv[j] }
__device__ float2 g_tab[NCH * (SZ - 1)];

// --- prologue: slope clipping -> cumsum -> recenter -> pair/diff table -----
__global__ void lipschitz_kernel(const float* __restrict__ coeff) {
    int c = threadIdx.x;
    if (c >= NCH) return;
    const float* cs = coeff + c * SZ;
    float vals[SZ];
    vals[0] = 0.0f;
    float acc = 0.0f;
    float prev = cs[0];
#pragma unroll
    for (int i = 1; i < SZ; ++i) {
        float cur = cs[i];
        float slope = fminf(fmaxf(cur - prev, 0.0f), GRID_F);
        acc += slope;
        vals[i] = acc;
        prev = cur;
    }
    float mid = vals[HALF];
    float2* dst = g_tab + c * (SZ - 1);
#pragma unroll
    for (int j = 0; j < SZ - 1; ++j) {
        float c0 = vals[j] - mid;
        float c1 = vals[j + 1] - mid;
        dst[j] = make_float2(c0, c1 - c0);
    }
}

// --- main elementwise spline eval ------------------------------------------
__global__ void __launch_bounds__(256)
spline_kernel(const float4* __restrict__ x,
              const float* __restrict__ scale,
              float4* __restrict__ out,
              int n4) {
    int i = blockIdx.x * blockDim.x + threadIdx.x;
    if (i >= n4) return;

    // element index = 4*i ; channel = (4*i / 16384) % 64 = (i >> 12) & 63
    int c = (i >> 12) & (NCH - 1);
    float s = __ldg(scale + c);
    float inv_s = __fdividef(1.0f, s);
    const float2* __restrict__ tab = g_tab + c * (SZ - 1);

    float4 v = x[i];
    float xin[4] = {v.x, v.y, v.z, v.w};
    float r[4];

#pragma unroll
    for (int k = 0; k < 4; ++k) {
        float xs = xin[k] * s;
        float xc = fminf(fmaxf(xs, CLAMP_LO), CLAMP_HI);
        float fl = floorf(fmaf(xc, INV_GRID, FLOOR_EPS));   // fl in [-25, 24]
        float fr = fmaf(xs, INV_GRID, -fl);                 // frac from UNCLAMPED xs
        int idx  = HALF + (int)fl;                          // in [0, 49]
        float2 p = __ldg(tab + idx);                        // {c0, c1-c0}
        r[k] = fmaf(fr, p.y, p.x) * inv_s;
    }

    out[i] = make_float4(r[0], r[1], r[2], r[3]);
}

extern "C" void kernel_launch(void* const* d_in, const int* in_sizes, int n_in,
                              void* d_out, int out_size) {
    const float* x     = (const float*)d_in[0];
    const float* coeff = (const float*)d_in[1];
    const float* scl   = (const float*)d_in[2];
    float* out = (float*)d_out;

    lipschitz_kernel<<<1, NCH>>>(coeff);

    int n  = out_size;        // 33554432
    int n4 = n / 4;           // 8388608
    int threads = 256;
    int blocks = (n4 + threads - 1) / threads;
    spline_kernel<<<blocks, threads>>>((const float4*)x, scl, (float4*)out, n4);
}